// round 3
// baseline (speedup 1.0000x reference)
#include <cuda_runtime.h>
#include <math.h>

#define PP  20000
#define MMR 20000
#define NN  16
#define DD  128
#define HH  8
#define DFF 512

// ---------------- scratch (static device memory; no allocations) ----------------
__device__ float g_q  [(size_t)PP * DD * 3];
__device__ float g_k  [(size_t)MMR * DD * 3];
__device__ float g_v  [(size_t)MMR * DD * 3];
__device__ float g_t2 [(size_t)PP * DD * 3];
__device__ float g_t2o[(size_t)PP * DD * 3];
__device__ float g_y  [(size_t)PP * DD * 3];
__device__ float g_h1 [(size_t)PP * DFF * 3];
__device__ float g_ff [(size_t)PP * DD * 3];

// Packed fp32x2 FMA (Blackwell): d = a*b + d per 32-bit lane, rn rounding.
__device__ __forceinline__ void fma2(float2& d, const float2 a, const float2 b)
{
    asm("fma.rn.f32x2 %0, %1, %2, %0;"
        : "+l"(*reinterpret_cast<unsigned long long*>(&d))
        : "l"(*reinterpret_cast<const unsigned long long*>(&a)),
          "l"(*reinterpret_cast<const unsigned long long*>(&b)));
}

// ---------------------------------------------------------------------------
// VN GEMM, Cout = 128: Y[p, o, i] = sum_c X[p, c, i] * W[c, o]
// CTA: 96 flat rows (32 points) x 128 outs, 256 threads, thread tile 6x8.
// Register-prefetch software pipeline over 16-wide k tiles.
// ---------------------------------------------------------------------------
template <int K>
__global__ void __launch_bounds__(256, 3)
vn_gemm3(const float* __restrict__ X, const float* __restrict__ W,
         float* __restrict__ Y)
{
    const int tid = threadIdx.x;
    const int tx  = tid & 15;     // 16 col groups (8 cols each)
    const int ty  = tid >> 4;     // 16 row groups (6 rows each)
    const int pb  = blockIdx.x * 32;

    __shared__ float  Xs[16 * 98];     // [k][flat row], pad to 98
    __shared__ float4 Wd[16 * 64];     // [k][16B dup unit] (128 outs)

    float2 acc[3][8] = {};

    // per-thread invariant load/store mappings
    int x_pt[6], x_off[6], x_sm[6];
    #pragma unroll
    for (int jj = 0; jj < 6; jj++) {
        int e = tid + 256 * jj;            // 1536 X elems per tile
        x_pt[jj]  = e / 48;
        x_off[jj] = e - x_pt[jj] * 48;
        x_sm[jj]  = (x_off[jj] / 3) * 98 + x_pt[jj] * 3 + (x_off[jj] % 3);
    }
    int w_k[8], w_o[8];
    #pragma unroll
    for (int jj = 0; jj < 8; jj++) {
        int e = tid + 256 * jj;            // 2048 W elems per tile
        w_k[jj] = e >> 7;
        w_o[jj] = e & 127;
    }

    float px[6], pw[8];
    // prologue: tile 0
    #pragma unroll
    for (int jj = 0; jj < 6; jj++)
        px[jj] = X[(size_t)(pb + x_pt[jj]) * (K * 3) + x_off[jj]];
    #pragma unroll
    for (int jj = 0; jj < 8; jj++)
        pw[jj] = W[(size_t)w_k[jj] * 128 + w_o[jj]];
    #pragma unroll
    for (int jj = 0; jj < 6; jj++) Xs[x_sm[jj]] = px[jj];
    #pragma unroll
    for (int jj = 0; jj < 8; jj++)
        reinterpret_cast<float2*>(Wd)[w_k[jj] * 128 + w_o[jj]] = make_float2(pw[jj], pw[jj]);

    #pragma unroll 1
    for (int c0 = 0; c0 < K; c0 += 16) {
        __syncthreads();
        const bool more = (c0 + 16 < K);
        if (more) {
            #pragma unroll
            for (int jj = 0; jj < 6; jj++)
                px[jj] = X[(size_t)(pb + x_pt[jj]) * (K * 3) + (c0 + 16) * 3 + x_off[jj]];
            #pragma unroll
            for (int jj = 0; jj < 8; jj++)
                pw[jj] = W[(size_t)(c0 + 16 + w_k[jj]) * 128 + w_o[jj]];
        }
        #pragma unroll
        for (int k = 0; k < 16; k++) {
            float2 A[3];
            #pragma unroll
            for (int m = 0; m < 3; m++)
                A[m] = *reinterpret_cast<const float2*>(&Xs[k * 98 + ty * 6 + 2 * m]);
            #pragma unroll
            for (int j = 0; j < 4; j++) {
                float4 w4 = Wd[k * 64 + tx + 16 * j];
                float2 W0 = make_float2(w4.x, w4.y);
                float2 W1 = make_float2(w4.z, w4.w);
                #pragma unroll
                for (int m = 0; m < 3; m++) {
                    fma2(acc[m][2 * j],     A[m], W0);
                    fma2(acc[m][2 * j + 1], A[m], W1);
                }
            }
        }
        __syncthreads();
        if (more) {
            #pragma unroll
            for (int jj = 0; jj < 6; jj++) Xs[x_sm[jj]] = px[jj];
            #pragma unroll
            for (int jj = 0; jj < 8; jj++)
                reinterpret_cast<float2*>(Wd)[w_k[jj] * 128 + w_o[jj]] = make_float2(pw[jj], pw[jj]);
        }
    }

    // store: thread owns points 2ty, 2ty+1 (local), 8 cols
    #pragma unroll
    for (int ptl = 0; ptl < 2; ptl++) {
        int pt = pb + 2 * ty + ptl;
        #pragma unroll
        for (int co = 0; co < 8; co++) {
            int o = 2 * (tx + 16 * (co >> 1)) + (co & 1);
            #pragma unroll
            for (int i = 0; i < 3; i++) {
                int r = 3 * ptl + i;
                float v = (r & 1) ? acc[r >> 1][co].y : acc[r >> 1][co].x;
                Y[(size_t)pt * 384 + o * 3 + i] = v;
            }
        }
    }
}

// ---------------------------------------------------------------------------
// FF1: h1 = vn_relu(Y @ W1, Y @ D1). CTA: 96 rows (32 pts) x 64 f, dual-W.
// 256 threads, thread tile 6 rows x 4 cols x 2 matrices, same pipeline.
// ---------------------------------------------------------------------------
__global__ void __launch_bounds__(256, 3)
vn_ff1b(const float* __restrict__ Yin, const float* __restrict__ W1,
        const float* __restrict__ D1, float* __restrict__ H1)
{
    const int tid = threadIdx.x;
    const int tx  = tid & 15;
    const int ty  = tid >> 4;
    const int pb  = blockIdx.y * 32;
    const int f0  = blockIdx.x * 64;

    __shared__ float  Xs[16 * 98];
    __shared__ float4 Wd[2][16 * 32];   // 64 outs each, dup

    float2 accA[3][4] = {};
    float2 accB[3][4] = {};

    int x_pt[6], x_off[6], x_sm[6];
    #pragma unroll
    for (int jj = 0; jj < 6; jj++) {
        int e = tid + 256 * jj;
        x_pt[jj]  = e / 48;
        x_off[jj] = e - x_pt[jj] * 48;
        x_sm[jj]  = (x_off[jj] / 3) * 98 + x_pt[jj] * 3 + (x_off[jj] % 3);
    }
    int w_k[4], w_o[4];
    #pragma unroll
    for (int jj = 0; jj < 4; jj++) {
        int e = tid + 256 * jj;            // 1024 per matrix
        w_k[jj] = e >> 6;
        w_o[jj] = e & 63;
    }

    float px[6], pa[4], pbw[4];
    #pragma unroll
    for (int jj = 0; jj < 6; jj++)
        px[jj] = Yin[(size_t)(pb + x_pt[jj]) * (DD * 3) + x_off[jj]];
    #pragma unroll
    for (int jj = 0; jj < 4; jj++) {
        pa[jj]  = W1[(size_t)w_k[jj] * DFF + f0 + w_o[jj]];
        pbw[jj] = D1[(size_t)w_k[jj] * DFF + f0 + w_o[jj]];
    }
    #pragma unroll
    for (int jj = 0; jj < 6; jj++) Xs[x_sm[jj]] = px[jj];
    #pragma unroll
    for (int jj = 0; jj < 4; jj++) {
        reinterpret_cast<float2*>(Wd[0])[w_k[jj] * 64 + w_o[jj]] = make_float2(pa[jj], pa[jj]);
        reinterpret_cast<float2*>(Wd[1])[w_k[jj] * 64 + w_o[jj]] = make_float2(pbw[jj], pbw[jj]);
    }

    #pragma unroll 1
    for (int c0 = 0; c0 < DD; c0 += 16) {
        __syncthreads();
        const bool more = (c0 + 16 < DD);
        if (more) {
            #pragma unroll
            for (int jj = 0; jj < 6; jj++)
                px[jj] = Yin[(size_t)(pb + x_pt[jj]) * (DD * 3) + (c0 + 16) * 3 + x_off[jj]];
            #pragma unroll
            for (int jj = 0; jj < 4; jj++) {
                pa[jj]  = W1[(size_t)(c0 + 16 + w_k[jj]) * DFF + f0 + w_o[jj]];
                pbw[jj] = D1[(size_t)(c0 + 16 + w_k[jj]) * DFF + f0 + w_o[jj]];
            }
        }
        #pragma unroll
        for (int k = 0; k < 16; k++) {
            float2 A[3];
            #pragma unroll
            for (int m = 0; m < 3; m++)
                A[m] = *reinterpret_cast<const float2*>(&Xs[k * 98 + ty * 6 + 2 * m]);
            #pragma unroll
            for (int j = 0; j < 2; j++) {
                float4 wa4 = Wd[0][k * 32 + tx + 16 * j];
                float4 wb4 = Wd[1][k * 32 + tx + 16 * j];
                float2 Wa0 = make_float2(wa4.x, wa4.y);
                float2 Wa1 = make_float2(wa4.z, wa4.w);
                float2 Wb0 = make_float2(wb4.x, wb4.y);
                float2 Wb1 = make_float2(wb4.z, wb4.w);
                #pragma unroll
                for (int m = 0; m < 3; m++) {
                    fma2(accA[m][2 * j],     A[m], Wa0);
                    fma2(accA[m][2 * j + 1], A[m], Wa1);
                    fma2(accB[m][2 * j],     A[m], Wb0);
                    fma2(accB[m][2 * j + 1], A[m], Wb1);
                }
            }
        }
        __syncthreads();
        if (more) {
            #pragma unroll
            for (int jj = 0; jj < 6; jj++) Xs[x_sm[jj]] = px[jj];
            #pragma unroll
            for (int jj = 0; jj < 4; jj++) {
                reinterpret_cast<float2*>(Wd[0])[w_k[jj] * 64 + w_o[jj]] = make_float2(pa[jj], pa[jj]);
                reinterpret_cast<float2*>(Wd[1])[w_k[jj] * 64 + w_o[jj]] = make_float2(pbw[jj], pbw[jj]);
            }
        }
    }

    #pragma unroll
    for (int ptl = 0; ptl < 2; ptl++) {
        int p = pb + 2 * ty + ptl;
        #pragma unroll
        for (int co = 0; co < 4; co++) {
            int o = f0 + 2 * (tx + 16 * (co >> 1)) + (co & 1);
            float a[3], b[3];
            #pragma unroll
            for (int i = 0; i < 3; i++) {
                int r = 3 * ptl + i;
                a[i] = (r & 1) ? accA[r >> 1][co].y : accA[r >> 1][co].x;
                b[i] = (r & 1) ? accB[r >> 1][co].y : accB[r >> 1][co].x;
            }
            float dot = a[0] * b[0] + a[1] * b[1] + a[2] * b[2];
            float ksq = b[0] * b[0] + b[1] * b[1] + b[2] * b[2];
            float s = (dot >= 0.0f) ? 0.0f : (dot / (ksq + 1e-6f));
            float* hp = H1 + (size_t)p * (DFF * 3) + (size_t)o * 3;
            hp[0] = a[0] - s * b[0];
            hp[1] = a[1] - s * b[1];
            hp[2] = a[2] - s * b[2];
        }
    }
}

// ---------------------------------------------------------------------------
// Attention: one CTA (128 threads) per point p. Thread = channel d.
// ---------------------------------------------------------------------------
__global__ void attn_kernel(const float* __restrict__ sh,
                            const float* __restrict__ dist,
                            const float* __restrict__ gw1,
                            const float* __restrict__ gb1,
                            const float* __restrict__ gw2,
                            const float* __restrict__ gb2,
                            const int* __restrict__ idxp)
{
    const int p = blockIdx.x;
    const int d = threadIdx.x;
    const int h = d >> 4;

    __shared__ float pos_s[NN][DD];
    __shared__ float sh_s[NN][3];
    __shared__ float att_s[NN][HH];
    __shared__ float rh_s[NN][HH];
    __shared__ int   idx_s[NN];
    __shared__ float w1_s[DD][HH];

    const float* qp = g_q + (size_t)p * (DD * 3) + d * 3;
    float q0 = qp[0], q1 = qp[1], q2 = qp[2];

    if (d < NN) idx_s[d] = idxp[(size_t)p * NN + d];
    if (d < NN * 3) ((float*)sh_s)[d] = sh[(size_t)p * ((NN + 1) * 3) + 3 + d];
    #pragma unroll
    for (int e = d; e < DD * HH; e += 128) ((float*)w1_s)[e] = gw1[e];
    __syncthreads();

    #pragma unroll 4
    for (int n = 0; n < NN; n++) {
        size_t base = (size_t)idx_s[n] * (DD * 3) + d * 3;
        float k0 = g_k[base + 0], k1 = g_k[base + 1], k2 = g_k[base + 2];
        float dot = q0 * k0 + q1 * k1 + q2 * k2;
        dot += __shfl_xor_sync(0xffffffffu, dot, 8);
        dot += __shfl_xor_sync(0xffffffffu, dot, 4);
        dot += __shfl_xor_sync(0xffffffffu, dot, 2);
        dot += __shfl_xor_sync(0xffffffffu, dot, 1);
        if ((d & 15) == 0) att_s[n][h] = dot;
        pos_s[n][d] = (k0 - q0) * sh_s[n][0] + (k1 - q1) * sh_s[n][1]
                    + (k2 - q2) * sh_s[n][2];
    }
    __syncthreads();

    {
        int n = d >> 3, j = d & 7;
        float acc = gb1[j];
        const float4* pv = reinterpret_cast<const float4*>(&pos_s[n][0]);
        #pragma unroll 8
        for (int c4 = 0; c4 < DD / 4; c4++) {
            float4 pp = pv[c4];
            acc += pp.x * w1_s[c4 * 4 + 0][j] + pp.y * w1_s[c4 * 4 + 1][j]
                 + pp.z * w1_s[c4 * 4 + 2][j] + pp.w * w1_s[c4 * 4 + 3][j];
        }
        rh_s[n][j] = fmaxf(acc, 0.0f);
    }
    __syncthreads();

    {
        int n = d >> 3, hh = d & 7;
        float acc = gb2[hh];
        #pragma unroll
        for (int j = 0; j < HH; j++) acc += rh_s[n][j] * gw2[j * HH + hh];
        float da = dist[(size_t)p * (NN * HH) + n * HH + hh];
        att_s[n][hh] = (att_s[n][hh] + acc + da) * 0.25f;
    }
    __syncthreads();

    if (d < HH) {
        float m = -1e30f;
        #pragma unroll
        for (int n = 0; n < NN; n++) m = fmaxf(m, att_s[n][d]);
        float s = 0.f;
        #pragma unroll
        for (int n = 0; n < NN; n++) { float e = expf(att_s[n][d] - m); att_s[n][d] = e; s += e; }
        float inv = 1.f / s;
        #pragma unroll
        for (int n = 0; n < NN; n++) att_s[n][d] *= inv;
    }
    __syncthreads();

    float o0 = 0.f, o1 = 0.f, o2 = 0.f;
    #pragma unroll 4
    for (int n = 0; n < NN; n++) {
        float a = att_s[n][h];
        const float* vp = g_v + (size_t)idx_s[n] * (DD * 3) + d * 3;
        o0 += a * vp[0];
        o1 += a * vp[1];
        o2 += a * vp[2];
    }
    float* op = g_t2 + (size_t)p * (DD * 3) + d * 3;
    op[0] = o0; op[1] = o1; op[2] = o2;
}

// ---------------------------------------------------------------------------
// Fused residual + vn_layernorm: O = vn_ln(A + B). grid P, block 128.
// ---------------------------------------------------------------------------
__global__ void vn_ln_kernel(const float* __restrict__ A,
                             const float* __restrict__ B,
                             const float* __restrict__ gam,
                             const float* __restrict__ bet,
                             float* __restrict__ O)
{
    const int p = blockIdx.x;
    const int d = threadIdx.x;
    size_t base = (size_t)p * (DD * 3) + d * 3;
    float z0 = A[base + 0] + B[base + 0];
    float z1 = A[base + 1] + B[base + 1];
    float z2 = A[base + 2] + B[base + 2];
    float n = sqrtf(z0 * z0 + z1 * z1 + z2 * z2);

    float s1 = n, s2 = n * n;
    #pragma unroll
    for (int off = 16; off; off >>= 1) {
        s1 += __shfl_xor_sync(0xffffffffu, s1, off);
        s2 += __shfl_xor_sync(0xffffffffu, s2, off);
    }
    __shared__ float sm1[4], sm2[4];
    int w = d >> 5;
    if ((d & 31) == 0) { sm1[w] = s1; sm2[w] = s2; }
    __syncthreads();
    float S1 = sm1[0] + sm1[1] + sm1[2] + sm1[3];
    float S2 = sm2[0] + sm2[1] + sm2[2] + sm2[3];
    float mu  = S1 * (1.0f / DD);
    float var = S2 * (1.0f / DD) - mu * mu;
    float nh  = (n - mu) * rsqrtf(var + 1e-5f) * gam[d] + bet[d];
    float sc  = nh / (n + 1e-6f);
    O[base + 0] = z0 * sc;
    O[base + 1] = z1 * sc;
    O[base + 2] = z2 * sc;
}

// ---------------------------------------------------------------------------
extern "C" void kernel_launch(void* const* d_in, const int* in_sizes, int n_in,
                              void* d_out, int out_size)
{
    const float* tgt   = (const float*)d_in[0];
    const float* mem   = (const float*)d_in[1];
    const float* sh    = (const float*)d_in[2];
    const float* dist  = (const float*)d_in[3];
    const float* Wq    = (const float*)d_in[4];
    const float* Wk    = (const float*)d_in[5];
    const float* Wv    = (const float*)d_in[6];
    const float* Wo    = (const float*)d_in[7];
    const float* gw1   = (const float*)d_in[8];
    const float* gb1   = (const float*)d_in[9];
    const float* gw2   = (const float*)d_in[10];
    const float* gb2   = (const float*)d_in[11];
    const float* ln1g  = (const float*)d_in[12];
    const float* ln1b  = (const float*)d_in[13];
    const float* ln2g  = (const float*)d_in[14];
    const float* ln2b  = (const float*)d_in[15];
    const float* ffw1  = (const float*)d_in[16];
    const float* ffd1  = (const float*)d_in[17];
    const float* ffw2  = (const float*)d_in[18];
    const int*   idxp  = (const int*)d_in[19];
    float* out = (float*)d_out;

    float *q, *k, *v, *t2, *t2o, *y, *h1, *ff;
    cudaGetSymbolAddress((void**)&q,   g_q);
    cudaGetSymbolAddress((void**)&k,   g_k);
    cudaGetSymbolAddress((void**)&v,   g_v);
    cudaGetSymbolAddress((void**)&t2,  g_t2);
    cudaGetSymbolAddress((void**)&t2o, g_t2o);
    cudaGetSymbolAddress((void**)&y,   g_y);
    cudaGetSymbolAddress((void**)&h1,  g_h1);
    cudaGetSymbolAddress((void**)&ff,  g_ff);

    const int NT = PP / 32;   // 625 point tiles

    vn_gemm3<DD><<<NT, 256>>>(tgt, Wq, q);
    vn_gemm3<DD><<<NT, 256>>>(mem, Wk, k);
    vn_gemm3<DD><<<NT, 256>>>(mem, Wv, v);

    attn_kernel<<<PP, 128>>>(sh, dist, gw1, gb1, gw2, gb2, idxp);

    vn_gemm3<DD><<<NT, 256>>>(t2, Wo, t2o);
    vn_ln_kernel<<<PP, 128>>>(tgt, t2o, ln1g, ln1b, y);

    vn_ff1b<<<dim3(DFF / 64, NT), 256>>>(y, ffw1, ffd1, h1);
    vn_gemm3<DFF><<<NT, 256>>>(h1, ffw2, ff);
    vn_ln_kernel<<<PP, 128>>>(y, ff, ln2g, ln2b, out);
}

// round 4
// speedup vs baseline: 1.0854x; 1.0854x over previous
#include <cuda_runtime.h>
#include <math.h>

#define PP  20000
#define MMR 20000
#define NN  16
#define DD  128
#define HH  8
#define DFF 512

// ---------------- scratch (static device memory; no allocations) ----------------
__device__ float g_q  [(size_t)PP * DD * 3];
__device__ float g_k  [(size_t)MMR * DD * 3];
__device__ float g_v  [(size_t)MMR * DD * 3];
__device__ float g_t2 [(size_t)PP * DD * 3];
__device__ float g_t2o[(size_t)PP * DD * 3];
__device__ float g_y  [(size_t)PP * DD * 3];
__device__ float g_h1 [(size_t)PP * DFF * 3];
__device__ float g_ff [(size_t)PP * DD * 3];

// Packed fp32x2 FMA (Blackwell): d = a*b + d per 32-bit lane, rn rounding.
__device__ __forceinline__ void fma2(float2& d, const float2 a, const float2 b)
{
    asm("fma.rn.f32x2 %0, %1, %2, %0;"
        : "+l"(*reinterpret_cast<unsigned long long*>(&d))
        : "l"(*reinterpret_cast<const unsigned long long*>(&a)),
          "l"(*reinterpret_cast<const unsigned long long*>(&b)));
}

// ---------------------------------------------------------------------------
// VN GEMM, Cout = 128: Y[p, o, i] = sum_c X[p, c, i] * W[c, o]
// Round-2 structure (128 thr, 12x8 thread tile) + register-prefetch pipeline.
// ---------------------------------------------------------------------------
template <int K>
__global__ void __launch_bounds__(128, 3)
vn_gemm2(const float* __restrict__ X, const float* __restrict__ W,
         float* __restrict__ Y)
{
    const int tid = threadIdx.x;
    const int tx  = tid & 15;     // 16 col groups
    const int ty  = tid >> 4;     // 8 row groups (12 flat rows each)
    const int pb  = blockIdx.x * 32;   // base point

    __shared__ float  Xs[16 * 98];     // [k][flat row], stride 98 (pad)
    __shared__ float4 Wd[16 * 64];     // [k][16B unit], dup pairs

    float2 acc[6][8] = {};

    // invariant tile mappings
    const int x_pt  = (tid * 12) / 48;          // 12 consecutive elems per thread
    const int x_off = (tid * 12) % 48;          // aligned: 12 | 48
    const float* xg = X + (size_t)(pb + x_pt) * (K * 3) + x_off;
    // W: thread loads 16 elems = rows (tid>>3)+{0,8}, 8 consecutive cols
    const int w_k0 = tid >> 4;                   // 0..7  (rows k0, k0+8)
    const int w_o0 = (tid & 15) * 8;             // 8 consecutive outs
    const float* wg = W + (size_t)w_k0 * 128 + w_o0;

    float px[12], pw[16];
    // prologue: tile 0
    #pragma unroll
    for (int jj = 0; jj < 12; jj++) px[jj] = xg[jj];
    #pragma unroll
    for (int jj = 0; jj < 8; jj++) { pw[jj] = wg[jj]; pw[8 + jj] = wg[8 * 128 + jj]; }

    #pragma unroll 1
    for (int c0 = 0; c0 < K; c0 += 16) {
        // STS current tile from staging regs
        #pragma unroll
        for (int jj = 0; jj < 12; jj++) {
            int off = x_off + jj;
            Xs[(off / 3) * 98 + x_pt * 3 + (off % 3)] = px[jj];
        }
        #pragma unroll
        for (int jj = 0; jj < 16; jj++) {
            int k = w_k0 + (jj >> 3) * 8;
            int o = w_o0 + (jj & 7);
            reinterpret_cast<float2*>(Wd)[k * 128 + o] = make_float2(pw[jj], pw[jj]);
        }
        __syncthreads();
        // issue next tile's LDGs (latency hidden under compute)
        const bool more = (c0 + 16 < K);
        if (more) {
            const float* xn = xg + (c0 + 16) * 3;
            const float* wn = wg + (size_t)(c0 + 16) * 128;
            #pragma unroll
            for (int jj = 0; jj < 12; jj++) px[jj] = xn[jj];
            #pragma unroll
            for (int jj = 0; jj < 8; jj++) { pw[jj] = wn[jj]; pw[8 + jj] = wn[8 * 128 + jj]; }
        }
        #pragma unroll
        for (int k = 0; k < 16; k++) {
            float2 A[6];
            #pragma unroll
            for (int m = 0; m < 6; m++)
                A[m] = *reinterpret_cast<const float2*>(&Xs[k * 98 + ty * 12 + 2 * m]);
            #pragma unroll
            for (int j = 0; j < 4; j++) {
                float4 w4 = Wd[k * 64 + tx + 16 * j];
                float2 W0 = make_float2(w4.x, w4.y);
                float2 W1 = make_float2(w4.z, w4.w);
                #pragma unroll
                for (int m = 0; m < 6; m++) {
                    fma2(acc[m][2 * j],     A[m], W0);
                    fma2(acc[m][2 * j + 1], A[m], W1);
                }
            }
        }
        __syncthreads();
    }

    #pragma unroll
    for (int r = 0; r < 12; r++) {
        int pt = pb + 4 * ty + r / 3;
        int i  = r % 3;
        #pragma unroll
        for (int co = 0; co < 8; co++) {
            int o = 2 * (tx + 16 * (co >> 1)) + (co & 1);
            float v = (r & 1) ? acc[r >> 1][co].y : acc[r >> 1][co].x;
            Y[(size_t)pt * 384 + o * 3 + i] = v;
        }
    }
}

// ---------------------------------------------------------------------------
// FF1: h1 = vn_relu(Y @ W1, Y @ D1). Round-2 structure + prefetch pipeline.
// CTA tile: 32 points x 64 f-outs; thread: 12 rows x 4 cols x 2 matrices.
// ---------------------------------------------------------------------------
__global__ void __launch_bounds__(128, 3)
vn_ff1_kernel(const float* __restrict__ Yin, const float* __restrict__ W1,
              const float* __restrict__ D1, float* __restrict__ H1)
{
    const int tid = threadIdx.x;
    const int tx  = tid & 15;
    const int ty  = tid >> 4;
    const int pb  = blockIdx.y * 32;
    const int f0  = blockIdx.x * 64;

    __shared__ float  Xs[16 * 98];
    __shared__ float4 Wd[2][16 * 32];

    float2 accA[6][4] = {};
    float2 accB[6][4] = {};

    const int x_pt  = (tid * 12) / 48;
    const int x_off = (tid * 12) % 48;
    const float* xg = Yin + (size_t)(pb + x_pt) * (DD * 3) + x_off;
    // W tiles: 16k x 64o per matrix -> 8 elems per thread per matrix
    const int w_k0 = tid >> 4;                   // rows k0, k0+8
    const int w_o0 = (tid & 15) * 4;             // 4 consecutive outs
    const float* wa_g = W1 + (size_t)w_k0 * DFF + f0 + w_o0;
    const float* wb_g = D1 + (size_t)w_k0 * DFF + f0 + w_o0;

    float px[12], pa[8], pbw[8];
    #pragma unroll
    for (int jj = 0; jj < 12; jj++) px[jj] = xg[jj];
    #pragma unroll
    for (int jj = 0; jj < 4; jj++) {
        pa[jj]      = wa_g[jj];
        pa[4 + jj]  = wa_g[(size_t)8 * DFF + jj];
        pbw[jj]     = wb_g[jj];
        pbw[4 + jj] = wb_g[(size_t)8 * DFF + jj];
    }

    #pragma unroll 1
    for (int c0 = 0; c0 < DD; c0 += 16) {
        #pragma unroll
        for (int jj = 0; jj < 12; jj++) {
            int off = x_off + jj;
            Xs[(off / 3) * 98 + x_pt * 3 + (off % 3)] = px[jj];
        }
        #pragma unroll
        for (int jj = 0; jj < 8; jj++) {
            int k = w_k0 + (jj >> 2) * 8;
            int o = w_o0 + (jj & 3);
            reinterpret_cast<float2*>(Wd[0])[k * 64 + o] = make_float2(pa[jj], pa[jj]);
            reinterpret_cast<float2*>(Wd[1])[k * 64 + o] = make_float2(pbw[jj], pbw[jj]);
        }
        __syncthreads();
        const bool more = (c0 + 16 < DD);
        if (more) {
            const float* xn  = xg + (c0 + 16) * 3;
            const float* wan = wa_g + (size_t)(c0 + 16) * DFF;
            const float* wbn = wb_g + (size_t)(c0 + 16) * DFF;
            #pragma unroll
            for (int jj = 0; jj < 12; jj++) px[jj] = xn[jj];
            #pragma unroll
            for (int jj = 0; jj < 4; jj++) {
                pa[jj]      = wan[jj];
                pa[4 + jj]  = wan[(size_t)8 * DFF + jj];
                pbw[jj]     = wbn[jj];
                pbw[4 + jj] = wbn[(size_t)8 * DFF + jj];
            }
        }
        #pragma unroll
        for (int k = 0; k < 16; k++) {
            float2 A[6];
            #pragma unroll
            for (int m = 0; m < 6; m++)
                A[m] = *reinterpret_cast<const float2*>(&Xs[k * 98 + ty * 12 + 2 * m]);
            #pragma unroll
            for (int j = 0; j < 2; j++) {
                float4 wa4 = Wd[0][k * 32 + tx + 16 * j];
                float4 wb4 = Wd[1][k * 32 + tx + 16 * j];
                float2 Wa0 = make_float2(wa4.x, wa4.y);
                float2 Wa1 = make_float2(wa4.z, wa4.w);
                float2 Wb0 = make_float2(wb4.x, wb4.y);
                float2 Wb1 = make_float2(wb4.z, wb4.w);
                #pragma unroll
                for (int m = 0; m < 6; m++) {
                    fma2(accA[m][2 * j],     A[m], Wa0);
                    fma2(accA[m][2 * j + 1], A[m], Wa1);
                    fma2(accB[m][2 * j],     A[m], Wb0);
                    fma2(accB[m][2 * j + 1], A[m], Wb1);
                }
            }
        }
        __syncthreads();
    }

    #pragma unroll
    for (int ptl = 0; ptl < 4; ptl++) {
        int p = pb + 4 * ty + ptl;
        #pragma unroll
        for (int co = 0; co < 4; co++) {
            int o = f0 + 2 * (tx + 16 * (co >> 1)) + (co & 1);
            float a[3], b[3];
            #pragma unroll
            for (int i = 0; i < 3; i++) {
                int r = 3 * ptl + i;
                a[i] = (r & 1) ? accA[r >> 1][co].y : accA[r >> 1][co].x;
                b[i] = (r & 1) ? accB[r >> 1][co].y : accB[r >> 1][co].x;
            }
            float dot = a[0] * b[0] + a[1] * b[1] + a[2] * b[2];
            float ksq = b[0] * b[0] + b[1] * b[1] + b[2] * b[2];
            float s = (dot >= 0.0f) ? 0.0f : (dot / (ksq + 1e-6f));
            float* hp = H1 + (size_t)p * (DFF * 3) + (size_t)o * 3;
            hp[0] = a[0] - s * b[0];
            hp[1] = a[1] - s * b[1];
            hp[2] = a[2] - s * b[2];
        }
    }
}

// ---------------------------------------------------------------------------
// Attention: one CTA (128 threads) per point p. Thread = channel d.
// ---------------------------------------------------------------------------
__global__ void attn_kernel(const float* __restrict__ sh,
                            const float* __restrict__ dist,
                            const float* __restrict__ gw1,
                            const float* __restrict__ gb1,
                            const float* __restrict__ gw2,
                            const float* __restrict__ gb2,
                            const int* __restrict__ idxp)
{
    const int p = blockIdx.x;
    const int d = threadIdx.x;
    const int h = d >> 4;

    __shared__ float pos_s[NN][DD];
    __shared__ float sh_s[NN][3];
    __shared__ float att_s[NN][HH];
    __shared__ float rh_s[NN][HH];
    __shared__ int   idx_s[NN];
    __shared__ float w1_s[DD][HH];

    const float* qp = g_q + (size_t)p * (DD * 3) + d * 3;
    float q0 = qp[0], q1 = qp[1], q2 = qp[2];

    if (d < NN) idx_s[d] = idxp[(size_t)p * NN + d];
    if (d < NN * 3) ((float*)sh_s)[d] = sh[(size_t)p * ((NN + 1) * 3) + 3 + d];
    #pragma unroll
    for (int e = d; e < DD * HH; e += 128) ((float*)w1_s)[e] = gw1[e];
    __syncthreads();

    #pragma unroll 4
    for (int n = 0; n < NN; n++) {
        size_t base = (size_t)idx_s[n] * (DD * 3) + d * 3;
        float k0 = g_k[base + 0], k1 = g_k[base + 1], k2 = g_k[base + 2];
        float dot = q0 * k0 + q1 * k1 + q2 * k2;
        dot += __shfl_xor_sync(0xffffffffu, dot, 8);
        dot += __shfl_xor_sync(0xffffffffu, dot, 4);
        dot += __shfl_xor_sync(0xffffffffu, dot, 2);
        dot += __shfl_xor_sync(0xffffffffu, dot, 1);
        if ((d & 15) == 0) att_s[n][h] = dot;
        pos_s[n][d] = (k0 - q0) * sh_s[n][0] + (k1 - q1) * sh_s[n][1]
                    + (k2 - q2) * sh_s[n][2];
    }
    __syncthreads();

    {
        int n = d >> 3, j = d & 7;
        float acc = gb1[j];
        const float4* pv = reinterpret_cast<const float4*>(&pos_s[n][0]);
        #pragma unroll 8
        for (int c4 = 0; c4 < DD / 4; c4++) {
            float4 pp = pv[c4];
            acc += pp.x * w1_s[c4 * 4 + 0][j] + pp.y * w1_s[c4 * 4 + 1][j]
                 + pp.z * w1_s[c4 * 4 + 2][j] + pp.w * w1_s[c4 * 4 + 3][j];
        }
        rh_s[n][j] = fmaxf(acc, 0.0f);
    }
    __syncthreads();

    {
        int n = d >> 3, hh = d & 7;
        float acc = gb2[hh];
        #pragma unroll
        for (int j = 0; j < HH; j++) acc += rh_s[n][j] * gw2[j * HH + hh];
        float da = dist[(size_t)p * (NN * HH) + n * HH + hh];
        att_s[n][hh] = (att_s[n][hh] + acc + da) * 0.25f;
    }
    __syncthreads();

    if (d < HH) {
        float m = -1e30f;
        #pragma unroll
        for (int n = 0; n < NN; n++) m = fmaxf(m, att_s[n][d]);
        float s = 0.f;
        #pragma unroll
        for (int n = 0; n < NN; n++) { float e = expf(att_s[n][d] - m); att_s[n][d] = e; s += e; }
        float inv = 1.f / s;
        #pragma unroll
        for (int n = 0; n < NN; n++) att_s[n][d] *= inv;
    }
    __syncthreads();

    float o0 = 0.f, o1 = 0.f, o2 = 0.f;
    #pragma unroll 4
    for (int n = 0; n < NN; n++) {
        float a = att_s[n][h];
        const float* vp = g_v + (size_t)idx_s[n] * (DD * 3) + d * 3;
        o0 += a * vp[0];
        o1 += a * vp[1];
        o2 += a * vp[2];
    }
    float* op = g_t2 + (size_t)p * (DD * 3) + d * 3;
    op[0] = o0; op[1] = o1; op[2] = o2;
}

// ---------------------------------------------------------------------------
// Fused residual + vn_layernorm: O = vn_ln(A + B). grid P, block 128.
// ---------------------------------------------------------------------------
__global__ void vn_ln_kernel(const float* __restrict__ A,
                             const float* __restrict__ B,
                             const float* __restrict__ gam,
                             const float* __restrict__ bet,
                             float* __restrict__ O)
{
    const int p = blockIdx.x;
    const int d = threadIdx.x;
    size_t base = (size_t)p * (DD * 3) + d * 3;
    float z0 = A[base + 0] + B[base + 0];
    float z1 = A[base + 1] + B[base + 1];
    float z2 = A[base + 2] + B[base + 2];
    float n = sqrtf(z0 * z0 + z1 * z1 + z2 * z2);

    float s1 = n, s2 = n * n;
    #pragma unroll
    for (int off = 16; off; off >>= 1) {
        s1 += __shfl_xor_sync(0xffffffffu, s1, off);
        s2 += __shfl_xor_sync(0xffffffffu, s2, off);
    }
    __shared__ float sm1[4], sm2[4];
    int w = d >> 5;
    if ((d & 31) == 0) { sm1[w] = s1; sm2[w] = s2; }
    __syncthreads();
    float S1 = sm1[0] + sm1[1] + sm1[2] + sm1[3];
    float S2 = sm2[0] + sm2[1] + sm2[2] + sm2[3];
    float mu  = S1 * (1.0f / DD);
    float var = S2 * (1.0f / DD) - mu * mu;
    float nh  = (n - mu) * rsqrtf(var + 1e-5f) * gam[d] + bet[d];
    float sc  = nh / (n + 1e-6f);
    O[base + 0] = z0 * sc;
    O[base + 1] = z1 * sc;
    O[base + 2] = z2 * sc;
}

// ---------------------------------------------------------------------------
extern "C" void kernel_launch(void* const* d_in, const int* in_sizes, int n_in,
                              void* d_out, int out_size)
{
    const float* tgt   = (const float*)d_in[0];
    const float* mem   = (const float*)d_in[1];
    const float* sh    = (const float*)d_in[2];
    const float* dist  = (const float*)d_in[3];
    const float* Wq    = (const float*)d_in[4];
    const float* Wk    = (const float*)d_in[5];
    const float* Wv    = (const float*)d_in[6];
    const float* Wo    = (const float*)d_in[7];
    const float* gw1   = (const float*)d_in[8];
    const float* gb1   = (const float*)d_in[9];
    const float* gw2   = (const float*)d_in[10];
    const float* gb2   = (const float*)d_in[11];
    const float* ln1g  = (const float*)d_in[12];
    const float* ln1b  = (const float*)d_in[13];
    const float* ln2g  = (const float*)d_in[14];
    const float* ln2b  = (const float*)d_in[15];
    const float* ffw1  = (const float*)d_in[16];
    const float* ffd1  = (const float*)d_in[17];
    const float* ffw2  = (const float*)d_in[18];
    const int*   idxp  = (const int*)d_in[19];
    float* out = (float*)d_out;

    float *q, *k, *v, *t2, *t2o, *y, *h1, *ff;
    cudaGetSymbolAddress((void**)&q,   g_q);
    cudaGetSymbolAddress((void**)&k,   g_k);
    cudaGetSymbolAddress((void**)&v,   g_v);
    cudaGetSymbolAddress((void**)&t2,  g_t2);
    cudaGetSymbolAddress((void**)&t2o, g_t2o);
    cudaGetSymbolAddress((void**)&y,   g_y);
    cudaGetSymbolAddress((void**)&h1,  g_h1);
    cudaGetSymbolAddress((void**)&ff,  g_ff);

    const int NT = PP / 32;   // 625 point tiles

    vn_gemm2<DD><<<NT, 128>>>(tgt, Wq, q);
    vn_gemm2<DD><<<NT, 128>>>(mem, Wk, k);
    vn_gemm2<DD><<<NT, 128>>>(mem, Wv, v);

    attn_kernel<<<PP, 128>>>(sh, dist, gw1, gb1, gw2, gb2, idxp);

    vn_gemm2<DD><<<NT, 128>>>(t2, Wo, t2o);
    vn_ln_kernel<<<PP, 128>>>(tgt, t2o, ln1g, ln1b, y);

    vn_ff1_kernel<<<dim3(DFF / 64, NT), 128>>>(y, ffw1, ffd1, h1);
    vn_gemm2<DFF><<<NT, 128>>>(h1, ffw2, ff);
    vn_ln_kernel<<<PP, 128>>>(y, ff, ln2g, ln2b, out);
}

// round 5
// speedup vs baseline: 1.3305x; 1.2258x over previous
#include <cuda_runtime.h>
#include <math.h>

#define PP  20000
#define MMR 20000
#define NN  16
#define DD  128
#define HH  8
#define DFF 512

// ---------------- scratch (static device memory; no allocations) ----------------
// q/k/v padded to 4 floats per channel for aligned float4 gathers in attention.
__device__ float g_q  [(size_t)PP * DD * 4];
__device__ float g_k  [(size_t)MMR * DD * 4];
__device__ float g_v  [(size_t)MMR * DD * 4];
__device__ float g_t2 [(size_t)PP * DD * 3];
__device__ float g_t2o[(size_t)PP * DD * 3];
__device__ float g_y  [(size_t)PP * DD * 3];
__device__ float g_h1 [(size_t)PP * DFF * 3];
__device__ float g_ff [(size_t)PP * DD * 3];

// Packed fp32x2 FMA (Blackwell): d = a*b + d per 32-bit lane, rn rounding.
__device__ __forceinline__ void fma2(float2& d, const float2 a, const float2 b)
{
    asm("fma.rn.f32x2 %0, %1, %2, %0;"
        : "+l"(*reinterpret_cast<unsigned long long*>(&d))
        : "l"(*reinterpret_cast<const unsigned long long*>(&a)),
          "l"(*reinterpret_cast<const unsigned long long*>(&b)));
}

// ---------------------------------------------------------------------------
// Col-split VN GEMM: Y[p, o, i] = sum_c X[p, c, i] * W[c, o], Cout = 128.
// Grid: 1250 CTAs = 625 point-tiles x 2 col-halves (94% wave efficiency
// at occupancy 3). CTA tile: 96 flat rows (32 pts) x 64 outs, k-chunk 32.
// 128 threads; thread tile 12 rows x 4 cols (f32x2-packed rows).
// OPAD=1: output padded to 4-float channel stride (float4 stores).
// ---------------------------------------------------------------------------
template <int K, int OPAD>
__global__ void __launch_bounds__(128, 3)
vn_gemm_cs(const float* __restrict__ X, const float* __restrict__ W,
           float* __restrict__ Y)
{
    const int tid = threadIdx.x;
    const int tx  = tid & 15;          // 16 col groups (4 cols each)
    const int ty  = tid >> 4;          // 8 row groups (12 flat rows each)
    const int pb  = (blockIdx.x >> 1) * 32;
    const int o0  = (blockIdx.x & 1) * 64;

    __shared__ float  Xs[32 * 98];     // [k][flat row], stride 98
    __shared__ float4 Wd[32 * 32];     // [k][16B dup unit] (64 outs)

    float2 acc[6][4] = {};

    // X loader: thread covers point pt, 24 consecutive floats at offset xoff
    const int x_pt  = tid >> 2;          // 0..31
    const int x_off = (tid & 3) * 24;    // 0,24,48,72
    const int x_c   = x_off / 3;         // multiple of 8
    // W loader: rows k0+{0,8,16,24}, 4 consecutive cols
    const int w_k0 = tid >> 4;
    const int w_o  = (tid & 15) * 4;

    #pragma unroll 1
    for (int c0 = 0; c0 < K; c0 += 32) {
        // ---- X tile: 32 pts x 96 floats (32 c x 3 i) ----
        const float* xg = X + (size_t)(pb + x_pt) * (K * 3) + c0 * 3 + x_off;
        #pragma unroll
        for (int q4 = 0; q4 < 6; q4++) {
            float4 xv = *reinterpret_cast<const float4*>(xg + q4 * 4);
            int g0 = q4 * 4;
            float vv[4] = {xv.x, xv.y, xv.z, xv.w};
            #pragma unroll
            for (int u = 0; u < 4; u++) {
                int g = g0 + u;
                Xs[(x_c + g / 3) * 98 + x_pt * 3 + (g % 3)] = vv[u];
            }
        }
        // ---- W tile: 32 k x 64 o, duplicated pairs ----
        #pragma unroll
        for (int kk = 0; kk < 4; kk++) {
            int k = w_k0 + kk * 8;
            float4 wv = *reinterpret_cast<const float4*>(
                W + (size_t)(c0 + k) * 128 + o0 + w_o);
            float2* wd2 = reinterpret_cast<float2*>(Wd) + k * 64 + w_o;
            wd2[0] = make_float2(wv.x, wv.x);
            wd2[1] = make_float2(wv.y, wv.y);
            wd2[2] = make_float2(wv.z, wv.z);
            wd2[3] = make_float2(wv.w, wv.w);
        }
        __syncthreads();
        #pragma unroll 8
        for (int k = 0; k < 32; k++) {
            float2 A[6];
            #pragma unroll
            for (int m = 0; m < 6; m++)
                A[m] = *reinterpret_cast<const float2*>(&Xs[k * 98 + ty * 12 + 2 * m]);
            #pragma unroll
            for (int j = 0; j < 2; j++) {
                float4 w4 = Wd[k * 32 + tx + 16 * j];
                float2 W0 = make_float2(w4.x, w4.y);
                float2 W1 = make_float2(w4.z, w4.w);
                #pragma unroll
                for (int m = 0; m < 6; m++) {
                    fma2(acc[m][2 * j],     A[m], W0);
                    fma2(acc[m][2 * j + 1], A[m], W1);
                }
            }
        }
        __syncthreads();
    }

    if (OPAD) {
        // padded layout: Y[pt*512 + o*4 + i], one float4 per (pt, o)
        #pragma unroll
        for (int ptl = 0; ptl < 4; ptl++) {
            int pt = pb + 4 * ty + ptl;
            #pragma unroll
            for (int co = 0; co < 4; co++) {
                int o = o0 + 2 * (tx + 16 * (co >> 1)) + (co & 1);
                float4 val;
                int r0 = 3 * ptl;
                val.x = (r0 & 1)       ? acc[r0 >> 1][co].y       : acc[r0 >> 1][co].x;
                val.y = ((r0 + 1) & 1) ? acc[(r0 + 1) >> 1][co].y : acc[(r0 + 1) >> 1][co].x;
                val.z = ((r0 + 2) & 1) ? acc[(r0 + 2) >> 1][co].y : acc[(r0 + 2) >> 1][co].x;
                val.w = 0.0f;
                *reinterpret_cast<float4*>(Y + (size_t)pt * 512 + o * 4) = val;
            }
        }
    } else {
        #pragma unroll
        for (int r = 0; r < 12; r++) {
            int pt = pb + 4 * ty + r / 3;
            int i  = r % 3;
            #pragma unroll
            for (int co = 0; co < 4; co++) {
                int o = o0 + 2 * (tx + 16 * (co >> 1)) + (co & 1);
                float v = (r & 1) ? acc[r >> 1][co].y : acc[r >> 1][co].x;
                Y[(size_t)pt * 384 + o * 3 + i] = v;
            }
        }
    }
}

// ---------------------------------------------------------------------------
// FF1: h1 = vn_relu(Y @ W1, Y @ D1). Round-2 structure, verbatim.
// CTA tile: 32 points x 64 f-outs; thread: 12 rows x 4 cols x 2 matrices.
// ---------------------------------------------------------------------------
__global__ void __launch_bounds__(128, 3)
vn_ff1_kernel(const float* __restrict__ Yin, const float* __restrict__ W1,
              const float* __restrict__ D1, float* __restrict__ H1)
{
    const int tid = threadIdx.x;
    const int tx  = tid & 15;
    const int ty  = tid >> 4;
    const int pb  = blockIdx.y * 32;
    const int f0  = blockIdx.x * 64;

    __shared__ float  Xs[16 * 98];
    __shared__ float4 Wd[2][16 * 32];

    float2 accA[6][4] = {};
    float2 accB[6][4] = {};

    #pragma unroll 1
    for (int c0 = 0; c0 < DD; c0 += 16) {
        #pragma unroll
        for (int jj = 0; jj < 12; jj++) {
            int e   = tid + 128 * jj;
            int pt  = e / 48;
            int off = e - pt * 48;
            float v = Yin[(size_t)(pb + pt) * (DD * 3) + c0 * 3 + off];
            Xs[(off / 3) * 98 + pt * 3 + (off % 3)] = v;
        }
        #pragma unroll
        for (int jj = 0; jj < 8; jj++) {
            int e = tid + 128 * jj;            // 1024 per matrix
            int k = e >> 6;
            int o = e & 63;
            float wa = W1[(size_t)(c0 + k) * DFF + f0 + o];
            float wb = D1[(size_t)(c0 + k) * DFF + f0 + o];
            reinterpret_cast<float2*>(Wd[0])[k * 64 + o] = make_float2(wa, wa);
            reinterpret_cast<float2*>(Wd[1])[k * 64 + o] = make_float2(wb, wb);
        }
        __syncthreads();
        #pragma unroll 4
        for (int k = 0; k < 16; k++) {
            float2 A[6];
            #pragma unroll
            for (int m = 0; m < 6; m++)
                A[m] = *reinterpret_cast<const float2*>(&Xs[k * 98 + ty * 12 + 2 * m]);
            #pragma unroll
            for (int j = 0; j < 2; j++) {
                float4 wa4 = Wd[0][k * 32 + tx + 16 * j];
                float4 wb4 = Wd[1][k * 32 + tx + 16 * j];
                float2 Wa0 = make_float2(wa4.x, wa4.y);
                float2 Wa1 = make_float2(wa4.z, wa4.w);
                float2 Wb0 = make_float2(wb4.x, wb4.y);
                float2 Wb1 = make_float2(wb4.z, wb4.w);
                #pragma unroll
                for (int m = 0; m < 6; m++) {
                    fma2(accA[m][2 * j],     A[m], Wa0);
                    fma2(accA[m][2 * j + 1], A[m], Wa1);
                    fma2(accB[m][2 * j],     A[m], Wb0);
                    fma2(accB[m][2 * j + 1], A[m], Wb1);
                }
            }
        }
        __syncthreads();
    }

    #pragma unroll
    for (int ptl = 0; ptl < 4; ptl++) {
        int p = pb + 4 * ty + ptl;
        #pragma unroll
        for (int co = 0; co < 4; co++) {
            int o = f0 + 2 * (tx + 16 * (co >> 1)) + (co & 1);
            float a[3], b[3];
            #pragma unroll
            for (int i = 0; i < 3; i++) {
                int r = 3 * ptl + i;
                a[i] = (r & 1) ? accA[r >> 1][co].y : accA[r >> 1][co].x;
                b[i] = (r & 1) ? accB[r >> 1][co].y : accB[r >> 1][co].x;
            }
            float dot = a[0] * b[0] + a[1] * b[1] + a[2] * b[2];
            float ksq = b[0] * b[0] + b[1] * b[1] + b[2] * b[2];
            float s = (dot >= 0.0f) ? 0.0f : (dot / (ksq + 1e-6f));
            float* hp = H1 + (size_t)p * (DFF * 3) + (size_t)o * 3;
            hp[0] = a[0] - s * b[0];
            hp[1] = a[1] - s * b[1];
            hp[2] = a[2] - s * b[2];
        }
    }
}

// ---------------------------------------------------------------------------
// Attention: one CTA (128 threads) per point p. Thread = channel d.
// q/k/v in padded 4-float layout -> single aligned LDG.128 per gather.
// ---------------------------------------------------------------------------
__global__ void attn_kernel(const float* __restrict__ sh,
                            const float* __restrict__ dist,
                            const float* __restrict__ gw1,
                            const float* __restrict__ gb1,
                            const float* __restrict__ gw2,
                            const float* __restrict__ gb2,
                            const int* __restrict__ idxp)
{
    const int p = blockIdx.x;
    const int d = threadIdx.x;
    const int h = d >> 4;

    __shared__ float pos_s[NN][DD];
    __shared__ float sh_s[NN][3];
    __shared__ float att_s[NN][HH];
    __shared__ float rh_s[NN][HH];
    __shared__ int   idx_s[NN];
    __shared__ float w1_s[DD][HH];

    const float4* q4 = reinterpret_cast<const float4*>(g_q);
    const float4* k4 = reinterpret_cast<const float4*>(g_k);
    const float4* v4 = reinterpret_cast<const float4*>(g_v);

    float4 qv = q4[(size_t)p * DD + d];
    float q0 = qv.x, q1 = qv.y, q2 = qv.z;

    if (d < NN) idx_s[d] = idxp[(size_t)p * NN + d];
    if (d < NN * 3) ((float*)sh_s)[d] = sh[(size_t)p * ((NN + 1) * 3) + 3 + d];
    #pragma unroll
    for (int e = d; e < DD * HH; e += 128) ((float*)w1_s)[e] = gw1[e];
    __syncthreads();

    #pragma unroll 4
    for (int n = 0; n < NN; n++) {
        float4 kv = k4[(size_t)idx_s[n] * DD + d];
        float k0 = kv.x, k1 = kv.y, k2 = kv.z;
        float dot = q0 * k0 + q1 * k1 + q2 * k2;
        dot += __shfl_xor_sync(0xffffffffu, dot, 8);
        dot += __shfl_xor_sync(0xffffffffu, dot, 4);
        dot += __shfl_xor_sync(0xffffffffu, dot, 2);
        dot += __shfl_xor_sync(0xffffffffu, dot, 1);
        if ((d & 15) == 0) att_s[n][h] = dot;
        pos_s[n][d] = (k0 - q0) * sh_s[n][0] + (k1 - q1) * sh_s[n][1]
                    + (k2 - q2) * sh_s[n][2];
    }
    __syncthreads();

    {
        int n = d >> 3, j = d & 7;
        float acc = gb1[j];
        const float4* pv = reinterpret_cast<const float4*>(&pos_s[n][0]);
        #pragma unroll 8
        for (int c4 = 0; c4 < DD / 4; c4++) {
            float4 pp = pv[c4];
            acc += pp.x * w1_s[c4 * 4 + 0][j] + pp.y * w1_s[c4 * 4 + 1][j]
                 + pp.z * w1_s[c4 * 4 + 2][j] + pp.w * w1_s[c4 * 4 + 3][j];
        }
        rh_s[n][j] = fmaxf(acc, 0.0f);
    }
    __syncthreads();

    {
        int n = d >> 3, hh = d & 7;
        float acc = gb2[hh];
        #pragma unroll
        for (int j = 0; j < HH; j++) acc += rh_s[n][j] * gw2[j * HH + hh];
        float da = dist[(size_t)p * (NN * HH) + n * HH + hh];
        att_s[n][hh] = (att_s[n][hh] + acc + da) * 0.25f;
    }
    __syncthreads();

    if (d < HH) {
        float m = -1e30f;
        #pragma unroll
        for (int n = 0; n < NN; n++) m = fmaxf(m, att_s[n][d]);
        float s = 0.f;
        #pragma unroll
        for (int n = 0; n < NN; n++) { float e = expf(att_s[n][d] - m); att_s[n][d] = e; s += e; }
        float inv = 1.f / s;
        #pragma unroll
        for (int n = 0; n < NN; n++) att_s[n][d] *= inv;
    }
    __syncthreads();

    float o0 = 0.f, o1 = 0.f, o2 = 0.f;
    #pragma unroll 4
    for (int n = 0; n < NN; n++) {
        float a = att_s[n][h];
        float4 vv = v4[(size_t)idx_s[n] * DD + d];
        o0 += a * vv.x;
        o1 += a * vv.y;
        o2 += a * vv.z;
    }
    float* op = g_t2 + (size_t)p * (DD * 3) + d * 3;
    op[0] = o0; op[1] = o1; op[2] = o2;
}

// ---------------------------------------------------------------------------
// Fused residual + vn_layernorm: O = vn_ln(A + B). grid P, block 128.
// ---------------------------------------------------------------------------
__global__ void vn_ln_kernel(const float* __restrict__ A,
                             const float* __restrict__ B,
                             const float* __restrict__ gam,
                             const float* __restrict__ bet,
                             float* __restrict__ O)
{
    const int p = blockIdx.x;
    const int d = threadIdx.x;
    size_t base = (size_t)p * (DD * 3) + d * 3;
    float z0 = A[base + 0] + B[base + 0];
    float z1 = A[base + 1] + B[base + 1];
    float z2 = A[base + 2] + B[base + 2];
    float n = sqrtf(z0 * z0 + z1 * z1 + z2 * z2);

    float s1 = n, s2 = n * n;
    #pragma unroll
    for (int off = 16; off; off >>= 1) {
        s1 += __shfl_xor_sync(0xffffffffu, s1, off);
        s2 += __shfl_xor_sync(0xffffffffu, s2, off);
    }
    __shared__ float sm1[4], sm2[4];
    int w = d >> 5;
    if ((d & 31) == 0) { sm1[w] = s1; sm2[w] = s2; }
    __syncthreads();
    float S1 = sm1[0] + sm1[1] + sm1[2] + sm1[3];
    float S2 = sm2[0] + sm2[1] + sm2[2] + sm2[3];
    float mu  = S1 * (1.0f / DD);
    float var = S2 * (1.0f / DD) - mu * mu;
    float nh  = (n - mu) * rsqrtf(var + 1e-5f) * gam[d] + bet[d];
    float sc  = nh / (n + 1e-6f);
    O[base + 0] = z0 * sc;
    O[base + 1] = z1 * sc;
    O[base + 2] = z2 * sc;
}

// ---------------------------------------------------------------------------
extern "C" void kernel_launch(void* const* d_in, const int* in_sizes, int n_in,
                              void* d_out, int out_size)
{
    const float* tgt   = (const float*)d_in[0];
    const float* mem   = (const float*)d_in[1];
    const float* sh    = (const float*)d_in[2];
    const float* dist  = (const float*)d_in[3];
    const float* Wq    = (const float*)d_in[4];
    const float* Wk    = (const float*)d_in[5];
    const float* Wv    = (const float*)d_in[6];
    const float* Wo    = (const float*)d_in[7];
    const float* gw1   = (const float*)d_in[8];
    const float* gb1   = (const float*)d_in[9];
    const float* gw2   = (const float*)d_in[10];
    const float* gb2   = (const float*)d_in[11];
    const float* ln1g  = (const float*)d_in[12];
    const float* ln1b  = (const float*)d_in[13];
    const float* ln2g  = (const float*)d_in[14];
    const float* ln2b  = (const float*)d_in[15];
    const float* ffw1  = (const float*)d_in[16];
    const float* ffd1  = (const float*)d_in[17];
    const float* ffw2  = (const float*)d_in[18];
    const int*   idxp  = (const int*)d_in[19];
    float* out = (float*)d_out;

    float *q, *k, *v, *t2, *t2o, *y, *h1, *ff;
    cudaGetSymbolAddress((void**)&q,   g_q);
    cudaGetSymbolAddress((void**)&k,   g_k);
    cudaGetSymbolAddress((void**)&v,   g_v);
    cudaGetSymbolAddress((void**)&t2,  g_t2);
    cudaGetSymbolAddress((void**)&t2o, g_t2o);
    cudaGetSymbolAddress((void**)&y,   g_y);
    cudaGetSymbolAddress((void**)&h1,  g_h1);
    cudaGetSymbolAddress((void**)&ff,  g_ff);

    const int NC = (PP / 32) * 2;   // 1250 col-split CTAs

    vn_gemm_cs<DD, 1><<<NC, 128>>>(tgt, Wq, q);
    vn_gemm_cs<DD, 1><<<NC, 128>>>(mem, Wk, k);
    vn_gemm_cs<DD, 1><<<NC, 128>>>(mem, Wv, v);

    attn_kernel<<<PP, 128>>>(sh, dist, gw1, gb1, gw2, gb2, idxp);

    vn_gemm_cs<DD, 0><<<NC, 128>>>(t2, Wo, t2o);
    vn_ln_kernel<<<PP, 128>>>(tgt, t2o, ln1g, ln1b, y);

    vn_ff1_kernel<<<dim3(DFF / 64, PP / 32), 128>>>(y, ffw1, ffd1, h1);
    vn_gemm_cs<DFF, 0><<<NC, 128>>>(h1, ffw2, ff);
    vn_ln_kernel<<<PP, 128>>>(y, ff, ln2g, ln2b, out);
}